// round 5
// baseline (speedup 1.0000x reference)
#include <cuda_runtime.h>

#define DM 2048      // d_model
#define NH 16        // heads
#define DH 128       // d_head
#define DL 512       // d_latent
#define BB 2         // batch
#define SS 2048      // seq
#define ROWS (BB * SS)   // 4096

// Scratch (allocation-free rule: __device__ globals). Total ~104 MB.
__device__ float g_q[ROWS * DM];     // [b*S+s][h*128+d]
__device__ float g_lat[ROWS * DL];
__device__ float g_kv[ROWS * DM];
__device__ float g_att[ROWS * DM];

// ---------------------------------------------------------------------------
// NN GEMM: C[M,N] = A[M,K] @ B[K,N], all row-major. M%128==0, N%128==0, K%8==0.
// 128x128 block tile, BK=8, 256 threads, 8x8 per-thread microtile.
// ---------------------------------------------------------------------------
__global__ __launch_bounds__(256) void gemm_nn(const float* __restrict__ A,
                                               const float* __restrict__ B,
                                               float* __restrict__ C,
                                               int M, int N, int K) {
    __shared__ float As[8][132];   // transposed A tile, pad 4 -> conflict-free
    __shared__ float Bs[8][128];

    const int tid = threadIdx.x;
    const int tx = tid & 15;
    const int ty = tid >> 4;
    const int bm = blockIdx.y << 7;
    const int bn = blockIdx.x << 7;

    const int arow = tid >> 1;          // 0..127
    const int acol = (tid & 1) << 2;    // 0 or 4
    const int brow = tid >> 5;          // 0..7
    const int bcol = (tid & 31) << 2;   // 0..124

    const float* Ap = A + (size_t)(bm + arow) * K + acol;
    const float* Bp = B + (size_t)brow * N + bn + bcol;

    float acc[8][8];
#pragma unroll
    for (int i = 0; i < 8; i++)
#pragma unroll
        for (int j = 0; j < 8; j++) acc[i][j] = 0.f;

    for (int k0 = 0; k0 < K; k0 += 8) {
        float4 av = *(const float4*)Ap;
        float4 bv = *(const float4*)Bp;
        As[acol + 0][arow] = av.x;
        As[acol + 1][arow] = av.y;
        As[acol + 2][arow] = av.z;
        As[acol + 3][arow] = av.w;
        *(float4*)&Bs[brow][bcol] = bv;
        __syncthreads();
#pragma unroll
        for (int kk = 0; kk < 8; kk++) {
            float a[8], b[8];
            *(float4*)(a)     = *(const float4*)&As[kk][ty * 8];
            *(float4*)(a + 4) = *(const float4*)&As[kk][ty * 8 + 4];
            *(float4*)(b)     = *(const float4*)&Bs[kk][tx * 8];
            *(float4*)(b + 4) = *(const float4*)&Bs[kk][tx * 8 + 4];
#pragma unroll
            for (int i = 0; i < 8; i++)
#pragma unroll
                for (int j = 0; j < 8; j++)
                    acc[i][j] = fmaf(a[i], b[j], acc[i][j]);
        }
        __syncthreads();
        Ap += 8;
        Bp += (size_t)8 * N;
    }

#pragma unroll
    for (int i = 0; i < 8; i++) {
        float* Cp = C + (size_t)(bm + ty * 8 + i) * N + bn + tx * 8;
        float4 c0 = make_float4(acc[i][0], acc[i][1], acc[i][2], acc[i][3]);
        float4 c1 = make_float4(acc[i][4], acc[i][5], acc[i][6], acc[i][7]);
        *(float4*)Cp = c0;
        *(float4*)(Cp + 4) = c1;
    }
}

// ---------------------------------------------------------------------------
// Fused flash attention. K == V (shared kv). grid = (S/64, H, B), 256 threads.
// Per block: 64 query rows x full Dh=128. Online softmax over 64-row KV tiles.
// smem: Qs[64][128] + Ks[64][129] + Ps[64][65] + m/l/alpha[64] = 83200 B.
// ---------------------------------------------------------------------------
__global__ __launch_bounds__(256) void mla_attn(const float* __restrict__ Q,
                                                const float* __restrict__ KV,
                                                float* __restrict__ O) {
    extern __shared__ float sm[];
    float* Qs   = sm;                  // 64 * 128
    float* Ks   = Qs + 64 * 128;       // 64 * 129 (pad 1)
    float* Ps   = Ks + 64 * 129;       // 64 * 65  (pad 1)
    float* mrow = Ps + 64 * 65;        // 64
    float* lrow = mrow + 64;           // 64
    float* arow = lrow + 64;           // 64

    const int tid = threadIdx.x;
    const int tx = tid & 15;           // 0..15 -> 4 S-cols / 8 O-cols
    const int ty = tid >> 4;           // 0..15 -> 4 rows
    const int qb = blockIdx.x;
    const int h  = blockIdx.y;
    const int b  = blockIdx.z;
    const float scale = 0.08838834764831843f;  // 1/sqrt(128)

    const float* qbase = Q  + ((size_t)b * SS + qb * 64) * DM + h * DH;
    const float* kbase = KV + (size_t)b * SS * DM + h * DH;

    // Load Q tile, pre-scaled
#pragma unroll
    for (int s = 0; s < 8; s++) {
        int idx = tid + s * 256;
        int r = idx >> 5;
        int c = (idx & 31) << 2;
        float4 v = *(const float4*)(qbase + (size_t)r * DM + c);
        v.x *= scale; v.y *= scale; v.z *= scale; v.w *= scale;
        *(float4*)&Qs[r * 128 + c] = v;
    }
    if (tid < 64) { mrow[tid] = -3.0e38f; lrow[tid] = 0.f; }

    float o[4][8];
#pragma unroll
    for (int i = 0; i < 4; i++)
#pragma unroll
        for (int j = 0; j < 8; j++) o[i][j] = 0.f;

    for (int t = 0; t < SS / 64; t++) {
        // Load KV tile [64][128] (stride-129 smem rows)
#pragma unroll
        for (int s = 0; s < 8; s++) {
            int idx = tid + s * 256;
            int r = idx >> 5;
            int c = (idx & 31) << 2;
            float4 v = *(const float4*)(kbase + (size_t)(t * 64 + r) * DM + c);
            float* d = &Ks[r * 129 + c];
            d[0] = v.x; d[1] = v.y; d[2] = v.z; d[3] = v.w;
        }
        __syncthreads();

        // S[r][c] = sum_d Qs[r][d] * Ks[c][d]  (Q already scaled)
        float sv[4][4];
#pragma unroll
        for (int i = 0; i < 4; i++)
#pragma unroll
            for (int j = 0; j < 4; j++) sv[i][j] = 0.f;

        for (int d0 = 0; d0 < 128; d0 += 8) {
            float qr[4][8];
#pragma unroll
            for (int i = 0; i < 4; i++) {
                *(float4*)(qr[i])     = *(const float4*)&Qs[(ty * 4 + i) * 128 + d0];
                *(float4*)(qr[i] + 4) = *(const float4*)&Qs[(ty * 4 + i) * 128 + d0 + 4];
            }
#pragma unroll
            for (int dd = 0; dd < 8; dd++) {
                float kr[4];
#pragma unroll
                for (int j = 0; j < 4; j++)
                    kr[j] = Ks[(tx * 4 + j) * 129 + d0 + dd];
#pragma unroll
                for (int i = 0; i < 4; i++)
#pragma unroll
                    for (int j = 0; j < 4; j++)
                        sv[i][j] = fmaf(qr[i][dd], kr[j], sv[i][j]);
            }
        }
#pragma unroll
        for (int i = 0; i < 4; i++)
#pragma unroll
            for (int j = 0; j < 4; j++)
                Ps[(ty * 4 + i) * 65 + tx * 4 + j] = sv[i][j];
        __syncthreads();

        // Online softmax: 4 threads per row, 16 cols each
        {
            int row = tid >> 2;
            int seg = tid & 3;
            float* pr = &Ps[row * 65 + seg * 16];
            float mloc = -3.0e38f;
#pragma unroll
            for (int c = 0; c < 16; c++) mloc = fmaxf(mloc, pr[c]);
            mloc = fmaxf(mloc, __shfl_xor_sync(0xffffffffu, mloc, 1));
            mloc = fmaxf(mloc, __shfl_xor_sync(0xffffffffu, mloc, 2));
            float mold = mrow[row];
            float mnew = fmaxf(mold, mloc);
            float sloc = 0.f;
#pragma unroll
            for (int c = 0; c < 16; c++) {
                float p = __expf(pr[c] - mnew);
                pr[c] = p;
                sloc += p;
            }
            sloc += __shfl_xor_sync(0xffffffffu, sloc, 1);
            sloc += __shfl_xor_sync(0xffffffffu, sloc, 2);
            if (seg == 0) {
                float al = __expf(mold - mnew);
                arow[row] = al;
                mrow[row] = mnew;
                lrow[row] = lrow[row] * al + sloc;
            }
        }
        __syncthreads();

        // O = alpha * O + P @ V  (V == Ks tile)
#pragma unroll
        for (int i = 0; i < 4; i++) {
            float al = arow[ty * 4 + i];
#pragma unroll
            for (int j = 0; j < 8; j++) o[i][j] *= al;
        }
#pragma unroll 8
        for (int kk = 0; kk < 64; kk++) {
            float pv[4];
#pragma unroll
            for (int i = 0; i < 4; i++) pv[i] = Ps[(ty * 4 + i) * 65 + kk];
            float vv[8];
            const float* vr = &Ks[kk * 129 + tx * 8];
#pragma unroll
            for (int j = 0; j < 8; j++) vv[j] = vr[j];
#pragma unroll
            for (int i = 0; i < 4; i++)
#pragma unroll
                for (int j = 0; j < 8; j++)
                    o[i][j] = fmaf(pv[i], vv[j], o[i][j]);
        }
        __syncthreads();
    }

    // Normalize and write out (same [b*S+s][h*128+d] layout)
#pragma unroll
    for (int i = 0; i < 4; i++) {
        float inv = 1.f / lrow[ty * 4 + i];
        float* op = O + ((size_t)b * SS + qb * 64 + ty * 4 + i) * DM + h * DH + tx * 8;
#pragma unroll
        for (int j = 0; j < 8; j++) op[j] = o[i][j] * inv;
    }
}

// ---------------------------------------------------------------------------
extern "C" void kernel_launch(void* const* d_in, const int* in_sizes, int n_in,
                              void* d_out, int out_size) {
    const float* x    = (const float*)d_in[0];   // [2,2048,2048]
    const float* W_q  = (const float*)d_in[1];   // [2048, 2048]
    const float* W_kd = (const float*)d_in[2];   // [2048, 512]
    const float* W_ku = (const float*)d_in[3];   // [512, 2048]
    const float* W_o  = (const float*)d_in[4];   // [2048, 2048]
    float* out = (float*)d_out;

    float *pq, *pl, *pkv, *pa;
    cudaGetSymbolAddress((void**)&pq,  g_q);
    cudaGetSymbolAddress((void**)&pl,  g_lat);
    cudaGetSymbolAddress((void**)&pkv, g_kv);
    cudaGetSymbolAddress((void**)&pa,  g_att);

    dim3 blk(256);

    // q = x @ W_q                    [4096 x 2048] * [2048 x 2048]
    gemm_nn<<<dim3(DM / 128, ROWS / 128), blk>>>(x, W_q, pq, ROWS, DM, DM);
    // latent = x @ W_kv_down         [4096 x 2048] * [2048 x 512]
    gemm_nn<<<dim3(DL / 128, ROWS / 128), blk>>>(x, W_kd, pl, ROWS, DL, DM);
    // kv = latent @ W_kv_up          [4096 x 512] * [512 x 2048]
    gemm_nn<<<dim3(DM / 128, ROWS / 128), blk>>>(pl, W_ku, pkv, ROWS, DM, DL);

    // fused attention
    size_t smem = (size_t)(64 * 128 + 64 * 129 + 64 * 65 + 3 * 64) * sizeof(float); // 83200
    cudaFuncSetAttribute(mla_attn, cudaFuncAttributeMaxDynamicSharedMemorySize, (int)smem);
    mla_attn<<<dim3(SS / 64, NH, BB), blk, smem>>>(pq, pkv, pa);

    // out = attn @ W_o               [4096 x 2048] * [2048 x 2048]
    gemm_nn<<<dim3(DM / 128, ROWS / 128), blk>>>(pa, W_o, out, ROWS, DM, DM);
}

// round 7
// speedup vs baseline: 1.1852x; 1.1852x over previous
#include <cuda_runtime.h>

#define DM 2048      // d_model
#define NH 16        // heads
#define DH 128       // d_head
#define DL 512       // d_latent
#define BB 2         // batch
#define SS 2048      // seq
#define ROWS (BB * SS)   // 4096

typedef unsigned long long ull;

// ---- f32x2 packed helpers (Blackwell FFMA2 path) ----
__device__ __forceinline__ ull ffma2(ull a, ull b, ull c) {
    ull d; asm("fma.rn.f32x2 %0, %1, %2, %3;" : "=l"(d) : "l"(a), "l"(b), "l"(c)); return d;
}
__device__ __forceinline__ ull mul2(ull a, ull b) {
    ull d; asm("mul.rn.f32x2 %0, %1, %2;" : "=l"(d) : "l"(a), "l"(b)); return d;
}
__device__ __forceinline__ ull pack2(float x, float y) {
    ull d; asm("mov.b64 %0, {%1, %2};" : "=l"(d) : "f"(x), "f"(y)); return d;
}
__device__ __forceinline__ float2 unpk2(ull v) {
    float x, y; asm("mov.b64 {%0, %1}, %2;" : "=f"(x), "=f"(y) : "l"(v)); return make_float2(x, y);
}

// Scratch (allocation-free rule: __device__ globals). Total ~104 MB.
__device__ float g_q[ROWS * DM];     // [b*S+s][h*128+d]
__device__ float g_lat[ROWS * DL];
__device__ float g_kv[ROWS * DM];
__device__ float g_att[ROWS * DM];

// ---------------------------------------------------------------------------
// NN GEMM with f32x2: C[M,N] = A[M,K] @ B[K,N], row-major. M,N %128==0, K%16==0.
// 128x128 block tile, BK=16, 256 threads, 8x8 per-thread microtile as 8x4 pairs.
// A staged DUPLICATED (As[kk][2r]=As[kk][2r+1]=A[r][kk]) -> dup operand = 1 LDS.
// B staged with 16B-chunk XOR(kk) swizzle; thread cols = {4tx..4tx+3, 64+4tx..}.
// ---------------------------------------------------------------------------
#define BK 16
__global__ __launch_bounds__(256, 2) void gemm_nn(const float* __restrict__ A,
                                                  const float* __restrict__ B,
                                                  float* __restrict__ C,
                                                  int M, int N, int K) {
    __shared__ __align__(16) float As[BK][264];   // dup layout, stride 264 words
    __shared__ __align__(16) float Bs[BK][128];   // chunk-swizzled

    const int tid = threadIdx.x;
    const int tx = tid & 15;
    const int ty = tid >> 4;
    const int bm = blockIdx.y << 7;
    const int bn = blockIdx.x << 7;

    const int arow = tid >> 1;           // 0..127
    const int acol = (tid & 1) << 3;     // 0 or 8 (8 kk values per thread)
    const int brow = tid >> 5;           // 0..7 (also loads brow+8)
    const int bcol = (tid & 31) << 2;    // 0..124
    const int cj   = tid & 31;           // logical 16B chunk for B store

    const float* Ap = A + (size_t)(bm + arow) * K + acol;
    const float* Bp = B + (size_t)brow * N + bn + bcol;

    ull acc[8][4] = {};   // 0ull == (0.f,0.f)

    for (int k0 = 0; k0 < K; k0 += BK) {
        float4 a0 = *(const float4*)Ap;
        float4 a1 = *(const float4*)(Ap + 4);
        float4 b0 = *(const float4*)Bp;
        float4 b1 = *(const float4*)(Bp + (size_t)8 * N);

        // A duplicated stores (8 kk slots per thread)
        *(ull*)&As[acol + 0][2 * arow] = pack2(a0.x, a0.x);
        *(ull*)&As[acol + 1][2 * arow] = pack2(a0.y, a0.y);
        *(ull*)&As[acol + 2][2 * arow] = pack2(a0.z, a0.z);
        *(ull*)&As[acol + 3][2 * arow] = pack2(a0.w, a0.w);
        *(ull*)&As[acol + 4][2 * arow] = pack2(a1.x, a1.x);
        *(ull*)&As[acol + 5][2 * arow] = pack2(a1.y, a1.y);
        *(ull*)&As[acol + 6][2 * arow] = pack2(a1.z, a1.z);
        *(ull*)&As[acol + 7][2 * arow] = pack2(a1.w, a1.w);
        // B swizzled stores: phys chunk = cj ^ (kk & 7); (brow+8)&7 == brow
        *(float4*)&Bs[brow][(cj ^ brow) << 2]     = b0;
        *(float4*)&Bs[brow + 8][(cj ^ brow) << 2] = b1;
        __syncthreads();

#pragma unroll
        for (int kk = 0; kk < BK; kk++) {
            ull a8[8], b4[4];
            *(ulonglong2*)&a8[0] = *(const ulonglong2*)&As[kk][16 * ty + 0];
            *(ulonglong2*)&a8[2] = *(const ulonglong2*)&As[kk][16 * ty + 4];
            *(ulonglong2*)&a8[4] = *(const ulonglong2*)&As[kk][16 * ty + 8];
            *(ulonglong2*)&a8[6] = *(const ulonglong2*)&As[kk][16 * ty + 12];
            const int k7 = kk & 7;
            *(ulonglong2*)&b4[0] = *(const ulonglong2*)&Bs[kk][(tx ^ k7) << 2];
            *(ulonglong2*)&b4[2] = *(const ulonglong2*)&Bs[kk][((tx + 16) ^ k7) << 2];
#pragma unroll
            for (int i = 0; i < 8; i++)
#pragma unroll
                for (int j = 0; j < 4; j++)
                    acc[i][j] = ffma2(a8[i], b4[j], acc[i][j]);
        }
        __syncthreads();
        Ap += BK;
        Bp += (size_t)BK * N;
    }

#pragma unroll
    for (int i = 0; i < 8; i++) {
        float* Cp = C + (size_t)(bm + ty * 8 + i) * N + bn;
        float2 p0 = unpk2(acc[i][0]), p1 = unpk2(acc[i][1]);
        float2 p2 = unpk2(acc[i][2]), p3 = unpk2(acc[i][3]);
        *(float4*)(Cp + 4 * tx)      = make_float4(p0.x, p0.y, p1.x, p1.y);
        *(float4*)(Cp + 64 + 4 * tx) = make_float4(p2.x, p2.y, p3.x, p3.y);
    }
}

// ---------------------------------------------------------------------------
// Fused flash attention with f32x2. K == V (shared kv). grid = (S/64, H, B).
// QK^T pairs along d (reduction) -> no dups; PV pairs along output d.
// Qs/Ks stride 130 words (even -> 8B-aligned b64, conflict-free patterns).
// smem: Qs[64*130] + Ks[64*130] + Ps[64*65] + stats = 83968 B -> 2 blocks/SM.
// ---------------------------------------------------------------------------
__global__ __launch_bounds__(256, 2) void mla_attn(const float* __restrict__ Q,
                                                   const float* __restrict__ KV,
                                                   float* __restrict__ O) {
    extern __shared__ __align__(16) float sm[];
    float* Qs   = sm;                  // 64 * 130
    float* Ks   = Qs + 64 * 130;       // 64 * 130
    float* Ps   = Ks + 64 * 130;       // 64 * 65
    float* mrow = Ps + 64 * 65;        // 64
    float* lrow = mrow + 64;           // 64
    float* arow = lrow + 64;           // 64

    const int tid = threadIdx.x;
    const int tx = tid & 15;           // S-cols tx+16j ; O-cols 2tx+32m
    const int ty = tid >> 4;           // rows ty*4+i
    const int qb = blockIdx.x;
    const int h  = blockIdx.y;
    const int b  = blockIdx.z;
    const float scale = 0.08838834764831843f;  // 1/sqrt(128)

    const float* qbase = Q  + ((size_t)b * SS + qb * 64) * DM + h * DH;
    const float* kbase = KV + (size_t)b * SS * DM + h * DH;

    // Load Q tile, pre-scaled, stride-130 rows (b64 stores)
#pragma unroll
    for (int s = 0; s < 8; s++) {
        int idx = tid + s * 256;
        int r = idx >> 5;
        int c = (idx & 31) << 2;
        float4 v = *(const float4*)(qbase + (size_t)r * DM + c);
        *(ull*)&Qs[r * 130 + c]     = pack2(v.x * scale, v.y * scale);
        *(ull*)&Qs[r * 130 + c + 2] = pack2(v.z * scale, v.w * scale);
    }
    if (tid < 64) { mrow[tid] = -3.0e38f; lrow[tid] = 0.f; }

    ull o2[4][4] = {};

    for (int t = 0; t < SS / 64; t++) {
        // Load KV tile [64][128] -> stride-130 rows
#pragma unroll
        for (int s = 0; s < 8; s++) {
            int idx = tid + s * 256;
            int r = idx >> 5;
            int c = (idx & 31) << 2;
            float4 v = *(const float4*)(kbase + (size_t)(t * 64 + r) * DM + c);
            *(ull*)&Ks[r * 130 + c]     = pack2(v.x, v.y);
            *(ull*)&Ks[r * 130 + c + 2] = pack2(v.z, v.w);
        }
        __syncthreads();

        // S = Qs @ Ks^T, pairs along d. Thread cols: tx + 16j.
        ull sv[4][4] = {};
#pragma unroll 4
        for (int p = 0; p < 64; p++) {
            ull qv[4], kv4[4];
#pragma unroll
            for (int i = 0; i < 4; i++)
                qv[i] = *(const ull*)&Qs[(ty * 4 + i) * 130 + 2 * p];
#pragma unroll
            for (int j = 0; j < 4; j++)
                kv4[j] = *(const ull*)&Ks[(tx + 16 * j) * 130 + 2 * p];
#pragma unroll
            for (int i = 0; i < 4; i++)
#pragma unroll
                for (int j = 0; j < 4; j++)
                    sv[i][j] = ffma2(qv[i], kv4[j], sv[i][j]);
        }
#pragma unroll
        for (int i = 0; i < 4; i++)
#pragma unroll
            for (int j = 0; j < 4; j++) {
                float2 e = unpk2(sv[i][j]);
                Ps[(ty * 4 + i) * 65 + tx + 16 * j] = e.x + e.y;
            }
        __syncthreads();

        // Online softmax: 4 threads per row, 16 cols each
        {
            int row = tid >> 2;
            int seg = tid & 3;
            float* pr = &Ps[row * 65 + seg * 16];
            float mloc = -3.0e38f;
#pragma unroll
            for (int c = 0; c < 16; c++) mloc = fmaxf(mloc, pr[c]);
            mloc = fmaxf(mloc, __shfl_xor_sync(0xffffffffu, mloc, 1));
            mloc = fmaxf(mloc, __shfl_xor_sync(0xffffffffu, mloc, 2));
            float mold = mrow[row];
            float mnew = fmaxf(mold, mloc);
            float sloc = 0.f;
#pragma unroll
            for (int c = 0; c < 16; c++) {
                float p = __expf(pr[c] - mnew);
                pr[c] = p;
                sloc += p;
            }
            sloc += __shfl_xor_sync(0xffffffffu, sloc, 1);
            sloc += __shfl_xor_sync(0xffffffffu, sloc, 2);
            if (seg == 0) {
                float al = __expf(mold - mnew);
                arow[row] = al;
                mrow[row] = mnew;
                lrow[row] = lrow[row] * al + sloc;
            }
        }
        __syncthreads();

        // O = alpha * O + P @ V  (V == Ks tile), pairs along output d
#pragma unroll
        for (int i = 0; i < 4; i++) {
            float al = arow[ty * 4 + i];
            ull al2 = pack2(al, al);
#pragma unroll
            for (int m = 0; m < 4; m++) o2[i][m] = mul2(o2[i][m], al2);
        }
#pragma unroll 4
        for (int kk = 0; kk < 64; kk++) {
            ull pd[4], vv[4];
#pragma unroll
            for (int i = 0; i < 4; i++) {
                float p = Ps[(ty * 4 + i) * 65 + kk];
                pd[i] = pack2(p, p);
            }
#pragma unroll
            for (int m = 0; m < 4; m++)
                vv[m] = *(const ull*)&Ks[kk * 130 + 32 * m + 2 * tx];
#pragma unroll
            for (int i = 0; i < 4; i++)
#pragma unroll
                for (int m = 0; m < 4; m++)
                    o2[i][m] = ffma2(pd[i], vv[m], o2[i][m]);
        }
        __syncthreads();
    }

    // Normalize and write out (cols 2tx + 32m, +1)
#pragma unroll
    for (int i = 0; i < 4; i++) {
        float inv = 1.f / lrow[ty * 4 + i];
        float* op = O + ((size_t)b * SS + qb * 64 + ty * 4 + i) * DM + h * DH;
#pragma unroll
        for (int m = 0; m < 4; m++) {
            float2 e = unpk2(o2[i][m]);
            *(float2*)(op + 32 * m + 2 * tx) = make_float2(e.x * inv, e.y * inv);
        }
    }
}

// ---------------------------------------------------------------------------
extern "C" void kernel_launch(void* const* d_in, const int* in_sizes, int n_in,
                              void* d_out, int out_size) {
    const float* x    = (const float*)d_in[0];   // [2,2048,2048]
    const float* W_q  = (const float*)d_in[1];   // [2048, 2048]
    const float* W_kd = (const float*)d_in[2];   // [2048, 512]
    const float* W_ku = (const float*)d_in[3];   // [512, 2048]
    const float* W_o  = (const float*)d_in[4];   // [2048, 2048]
    float* out = (float*)d_out;

    float *pq, *pl, *pkv, *pa;
    cudaGetSymbolAddress((void**)&pq,  g_q);
    cudaGetSymbolAddress((void**)&pl,  g_lat);
    cudaGetSymbolAddress((void**)&pkv, g_kv);
    cudaGetSymbolAddress((void**)&pa,  g_att);

    dim3 blk(256);

    // q = x @ W_q                    [4096 x 2048] * [2048 x 2048]
    gemm_nn<<<dim3(DM / 128, ROWS / 128), blk>>>(x, W_q, pq, ROWS, DM, DM);
    // latent = x @ W_kv_down         [4096 x 2048] * [2048 x 512]
    gemm_nn<<<dim3(DL / 128, ROWS / 128), blk>>>(x, W_kd, pl, ROWS, DL, DM);
    // kv = latent @ W_kv_up          [4096 x 512] * [512 x 2048]
    gemm_nn<<<dim3(DM / 128, ROWS / 128), blk>>>(pl, W_ku, pkv, ROWS, DM, DL);

    // fused attention
    size_t smem = (size_t)(64 * 130 * 2 + 64 * 65 + 3 * 64) * sizeof(float); // 83968
    cudaFuncSetAttribute(mla_attn, cudaFuncAttributeMaxDynamicSharedMemorySize, (int)smem);
    mla_attn<<<dim3(SS / 64, NH, BB), blk, smem>>>(pq, pkv, pa);

    // out = attn @ W_o               [4096 x 2048] * [2048 x 2048]
    gemm_nn<<<dim3(DM / 128, ROWS / 128), blk>>>(pa, W_o, out, ROWS, DM, DM);
}

// round 8
// speedup vs baseline: 1.1856x; 1.0004x over previous
#include <cuda_runtime.h>

#define DM 2048      // d_model
#define NH 16        // heads
#define DH 128       // d_head
#define DL 512       // d_latent
#define BB 2         // batch
#define SS 2048      // seq
#define ROWS (BB * SS)   // 4096

typedef unsigned long long ull;

// ---- f32x2 packed helpers (Blackwell FFMA2 path) ----
__device__ __forceinline__ ull ffma2(ull a, ull b, ull c) {
    ull d; asm("fma.rn.f32x2 %0, %1, %2, %3;" : "=l"(d) : "l"(a), "l"(b), "l"(c)); return d;
}
__device__ __forceinline__ ull mul2(ull a, ull b) {
    ull d; asm("mul.rn.f32x2 %0, %1, %2;" : "=l"(d) : "l"(a), "l"(b)); return d;
}
__device__ __forceinline__ ull pack2(float x, float y) {
    ull d; asm("mov.b64 %0, {%1, %2};" : "=l"(d) : "f"(x), "f"(y)); return d;
}
__device__ __forceinline__ float2 unpk2(ull v) {
    float x, y; asm("mov.b64 {%0, %1}, %2;" : "=f"(x), "=f"(y) : "l"(v)); return make_float2(x, y);
}

// Scratch (allocation-free rule: __device__ globals). Total ~104 MB.
__device__ float g_q[ROWS * DM];     // [b*S+s][h*128+d]
__device__ float g_lat[ROWS * DL];
__device__ float g_kv[ROWS * DM];
__device__ float g_att[ROWS * DM];

// ---------------------------------------------------------------------------
// NN GEMM with f32x2: C[M,N] = A[M,K] @ B[K,N], row-major. M,N %128==0, K%16==0.
// 128x128 block tile, BK=16, 256 threads, 8x8 per-thread microtile as 8x4 pairs.
// A staged DUPLICATED (As[kk][2r]=As[kk][2r+1]=A[r][kk]) -> dup operand = 1 LDS.
// B staged with 16B-chunk XOR(kk) swizzle; thread cols = {4tx..4tx+3, 64+4tx..}.
// ---------------------------------------------------------------------------
#define BK 16
__global__ __launch_bounds__(256, 2) void gemm_nn(const float* __restrict__ A,
                                                  const float* __restrict__ B,
                                                  float* __restrict__ C,
                                                  int M, int N, int K) {
    __shared__ __align__(16) float As[BK][264];   // dup layout, stride 264 words
    __shared__ __align__(16) float Bs[BK][128];   // chunk-swizzled

    const int tid = threadIdx.x;
    const int tx = tid & 15;
    const int ty = tid >> 4;
    const int bm = blockIdx.y << 7;
    const int bn = blockIdx.x << 7;

    const int arow = tid >> 1;           // 0..127
    const int acol = (tid & 1) << 3;     // 0 or 8 (8 kk values per thread)
    const int brow = tid >> 5;           // 0..7 (also loads brow+8)
    const int bcol = (tid & 31) << 2;    // 0..124
    const int cj   = tid & 31;           // logical 16B chunk for B store

    const float* Ap = A + (size_t)(bm + arow) * K + acol;
    const float* Bp = B + (size_t)brow * N + bn + bcol;

    ull acc[8][4] = {};   // 0ull == (0.f,0.f)

    for (int k0 = 0; k0 < K; k0 += BK) {
        float4 a0 = *(const float4*)Ap;
        float4 a1 = *(const float4*)(Ap + 4);
        float4 b0 = *(const float4*)Bp;
        float4 b1 = *(const float4*)(Bp + (size_t)8 * N);

        // A duplicated stores (8 kk slots per thread)
        *(ull*)&As[acol + 0][2 * arow] = pack2(a0.x, a0.x);
        *(ull*)&As[acol + 1][2 * arow] = pack2(a0.y, a0.y);
        *(ull*)&As[acol + 2][2 * arow] = pack2(a0.z, a0.z);
        *(ull*)&As[acol + 3][2 * arow] = pack2(a0.w, a0.w);
        *(ull*)&As[acol + 4][2 * arow] = pack2(a1.x, a1.x);
        *(ull*)&As[acol + 5][2 * arow] = pack2(a1.y, a1.y);
        *(ull*)&As[acol + 6][2 * arow] = pack2(a1.z, a1.z);
        *(ull*)&As[acol + 7][2 * arow] = pack2(a1.w, a1.w);
        // B swizzled stores: phys chunk = cj ^ (kk & 7); (brow+8)&7 == brow
        *(float4*)&Bs[brow][(cj ^ brow) << 2]     = b0;
        *(float4*)&Bs[brow + 8][(cj ^ brow) << 2] = b1;
        __syncthreads();

#pragma unroll
        for (int kk = 0; kk < BK; kk++) {
            ull a8[8], b4[4];
            *(ulonglong2*)&a8[0] = *(const ulonglong2*)&As[kk][16 * ty + 0];
            *(ulonglong2*)&a8[2] = *(const ulonglong2*)&As[kk][16 * ty + 4];
            *(ulonglong2*)&a8[4] = *(const ulonglong2*)&As[kk][16 * ty + 8];
            *(ulonglong2*)&a8[6] = *(const ulonglong2*)&As[kk][16 * ty + 12];
            const int k7 = kk & 7;
            *(ulonglong2*)&b4[0] = *(const ulonglong2*)&Bs[kk][(tx ^ k7) << 2];
            *(ulonglong2*)&b4[2] = *(const ulonglong2*)&Bs[kk][((tx + 16) ^ k7) << 2];
#pragma unroll
            for (int i = 0; i < 8; i++)
#pragma unroll
                for (int j = 0; j < 4; j++)
                    acc[i][j] = ffma2(a8[i], b4[j], acc[i][j]);
        }
        __syncthreads();
        Ap += BK;
        Bp += (size_t)BK * N;
    }

#pragma unroll
    for (int i = 0; i < 8; i++) {
        float* Cp = C + (size_t)(bm + ty * 8 + i) * N + bn;
        float2 p0 = unpk2(acc[i][0]), p1 = unpk2(acc[i][1]);
        float2 p2 = unpk2(acc[i][2]), p3 = unpk2(acc[i][3]);
        *(float4*)(Cp + 4 * tx)      = make_float4(p0.x, p0.y, p1.x, p1.y);
        *(float4*)(Cp + 64 + 4 * tx) = make_float4(p2.x, p2.y, p3.x, p3.y);
    }
}

// ---------------------------------------------------------------------------
// Fused flash attention with f32x2. K == V (shared kv). grid = (S/64, H, B).
// QK^T pairs along d (reduction) -> no dups; PV pairs along output d.
// Qs/Ks stride 130 words (even -> 8B-aligned b64, conflict-free patterns).
// smem: Qs[64*130] + Ks[64*130] + Ps[64*65] + stats = 83968 B -> 2 blocks/SM.
// ---------------------------------------------------------------------------
__global__ __launch_bounds__(256, 2) void mla_attn(const float* __restrict__ Q,
                                                   const float* __restrict__ KV,
                                                   float* __restrict__ O) {
    extern __shared__ __align__(16) float sm[];
    float* Qs   = sm;                  // 64 * 130
    float* Ks   = Qs + 64 * 130;       // 64 * 130
    float* Ps   = Ks + 64 * 130;       // 64 * 65
    float* mrow = Ps + 64 * 65;        // 64
    float* lrow = mrow + 64;           // 64
    float* arow = lrow + 64;           // 64

    const int tid = threadIdx.x;
    const int tx = tid & 15;           // S-cols tx+16j ; O-cols 2tx+32m
    const int ty = tid >> 4;           // rows ty*4+i
    const int qb = blockIdx.x;
    const int h  = blockIdx.y;
    const int b  = blockIdx.z;
    const float scale = 0.08838834764831843f;  // 1/sqrt(128)

    const float* qbase = Q  + ((size_t)b * SS + qb * 64) * DM + h * DH;
    const float* kbase = KV + (size_t)b * SS * DM + h * DH;

    // Load Q tile, pre-scaled, stride-130 rows (b64 stores)
#pragma unroll
    for (int s = 0; s < 8; s++) {
        int idx = tid + s * 256;
        int r = idx >> 5;
        int c = (idx & 31) << 2;
        float4 v = *(const float4*)(qbase + (size_t)r * DM + c);
        *(ull*)&Qs[r * 130 + c]     = pack2(v.x * scale, v.y * scale);
        *(ull*)&Qs[r * 130 + c + 2] = pack2(v.z * scale, v.w * scale);
    }
    if (tid < 64) { mrow[tid] = -3.0e38f; lrow[tid] = 0.f; }

    ull o2[4][4] = {};

    for (int t = 0; t < SS / 64; t++) {
        // Load KV tile [64][128] -> stride-130 rows
#pragma unroll
        for (int s = 0; s < 8; s++) {
            int idx = tid + s * 256;
            int r = idx >> 5;
            int c = (idx & 31) << 2;
            float4 v = *(const float4*)(kbase + (size_t)(t * 64 + r) * DM + c);
            *(ull*)&Ks[r * 130 + c]     = pack2(v.x, v.y);
            *(ull*)&Ks[r * 130 + c + 2] = pack2(v.z, v.w);
        }
        __syncthreads();

        // S = Qs @ Ks^T, pairs along d. Thread cols: tx + 16j.
        ull sv[4][4] = {};
#pragma unroll 4
        for (int p = 0; p < 64; p++) {
            ull qv[4], kv4[4];
#pragma unroll
            for (int i = 0; i < 4; i++)
                qv[i] = *(const ull*)&Qs[(ty * 4 + i) * 130 + 2 * p];
#pragma unroll
            for (int j = 0; j < 4; j++)
                kv4[j] = *(const ull*)&Ks[(tx + 16 * j) * 130 + 2 * p];
#pragma unroll
            for (int i = 0; i < 4; i++)
#pragma unroll
                for (int j = 0; j < 4; j++)
                    sv[i][j] = ffma2(qv[i], kv4[j], sv[i][j]);
        }
#pragma unroll
        for (int i = 0; i < 4; i++)
#pragma unroll
            for (int j = 0; j < 4; j++) {
                float2 e = unpk2(sv[i][j]);
                Ps[(ty * 4 + i) * 65 + tx + 16 * j] = e.x + e.y;
            }
        __syncthreads();

        // Online softmax: 4 threads per row, 16 cols each
        {
            int row = tid >> 2;
            int seg = tid & 3;
            float* pr = &Ps[row * 65 + seg * 16];
            float mloc = -3.0e38f;
#pragma unroll
            for (int c = 0; c < 16; c++) mloc = fmaxf(mloc, pr[c]);
            mloc = fmaxf(mloc, __shfl_xor_sync(0xffffffffu, mloc, 1));
            mloc = fmaxf(mloc, __shfl_xor_sync(0xffffffffu, mloc, 2));
            float mold = mrow[row];
            float mnew = fmaxf(mold, mloc);
            float sloc = 0.f;
#pragma unroll
            for (int c = 0; c < 16; c++) {
                float p = __expf(pr[c] - mnew);
                pr[c] = p;
                sloc += p;
            }
            sloc += __shfl_xor_sync(0xffffffffu, sloc, 1);
            sloc += __shfl_xor_sync(0xffffffffu, sloc, 2);
            if (seg == 0) {
                float al = __expf(mold - mnew);
                arow[row] = al;
                mrow[row] = mnew;
                lrow[row] = lrow[row] * al + sloc;
            }
        }
        __syncthreads();

        // O = alpha * O + P @ V  (V == Ks tile), pairs along output d
#pragma unroll
        for (int i = 0; i < 4; i++) {
            float al = arow[ty * 4 + i];
            ull al2 = pack2(al, al);
#pragma unroll
            for (int m = 0; m < 4; m++) o2[i][m] = mul2(o2[i][m], al2);
        }
#pragma unroll 4
        for (int kk = 0; kk < 64; kk++) {
            ull pd[4], vv[4];
#pragma unroll
            for (int i = 0; i < 4; i++) {
                float p = Ps[(ty * 4 + i) * 65 + kk];
                pd[i] = pack2(p, p);
            }
#pragma unroll
            for (int m = 0; m < 4; m++)
                vv[m] = *(const ull*)&Ks[kk * 130 + 32 * m + 2 * tx];
#pragma unroll
            for (int i = 0; i < 4; i++)
#pragma unroll
                for (int m = 0; m < 4; m++)
                    o2[i][m] = ffma2(pd[i], vv[m], o2[i][m]);
        }
        __syncthreads();
    }

    // Normalize and write out (cols 2tx + 32m, +1)
#pragma unroll
    for (int i = 0; i < 4; i++) {
        float inv = 1.f / lrow[ty * 4 + i];
        float* op = O + ((size_t)b * SS + qb * 64 + ty * 4 + i) * DM + h * DH;
#pragma unroll
        for (int m = 0; m < 4; m++) {
            float2 e = unpk2(o2[i][m]);
            *(float2*)(op + 32 * m + 2 * tx) = make_float2(e.x * inv, e.y * inv);
        }
    }
}

// ---------------------------------------------------------------------------
extern "C" void kernel_launch(void* const* d_in, const int* in_sizes, int n_in,
                              void* d_out, int out_size) {
    const float* x    = (const float*)d_in[0];   // [2,2048,2048]
    const float* W_q  = (const float*)d_in[1];   // [2048, 2048]
    const float* W_kd = (const float*)d_in[2];   // [2048, 512]
    const float* W_ku = (const float*)d_in[3];   // [512, 2048]
    const float* W_o  = (const float*)d_in[4];   // [2048, 2048]
    float* out = (float*)d_out;

    float *pq, *pl, *pkv, *pa;
    cudaGetSymbolAddress((void**)&pq,  g_q);
    cudaGetSymbolAddress((void**)&pl,  g_lat);
    cudaGetSymbolAddress((void**)&pkv, g_kv);
    cudaGetSymbolAddress((void**)&pa,  g_att);

    dim3 blk(256);

    // q = x @ W_q                    [4096 x 2048] * [2048 x 2048]
    gemm_nn<<<dim3(DM / 128, ROWS / 128), blk>>>(x, W_q, pq, ROWS, DM, DM);
    // latent = x @ W_kv_down         [4096 x 2048] * [2048 x 512]
    gemm_nn<<<dim3(DL / 128, ROWS / 128), blk>>>(x, W_kd, pl, ROWS, DL, DM);
    // kv = latent @ W_kv_up          [4096 x 512] * [512 x 2048]
    gemm_nn<<<dim3(DM / 128, ROWS / 128), blk>>>(pl, W_ku, pkv, ROWS, DM, DL);

    // fused attention
    size_t smem = (size_t)(64 * 130 * 2 + 64 * 65 + 3 * 64) * sizeof(float); // 83968
    cudaFuncSetAttribute(mla_attn, cudaFuncAttributeMaxDynamicSharedMemorySize, (int)smem);
    mla_attn<<<dim3(SS / 64, NH, BB), blk, smem>>>(pq, pkv, pa);

    // out = attn @ W_o               [4096 x 2048] * [2048 x 2048]
    gemm_nn<<<dim3(DM / 128, ROWS / 128), blk>>>(pa, W_o, out, ROWS, DM, DM);
}

// round 10
// speedup vs baseline: 1.8613x; 1.5699x over previous
#include <cuda_runtime.h>
#include <cuda_bf16.h>

#define DM 2048      // d_model
#define NH 16        // heads
#define DH 128       // d_head
#define DL 512       // d_latent
#define BB 2         // batch
#define SS 2048      // seq
#define ROWS (BB * SS)   // 4096

typedef unsigned long long ull;
typedef unsigned int u32;

// ---- f32x2 packed helpers (attention kernel) ----
__device__ __forceinline__ ull ffma2(ull a, ull b, ull c) {
    ull d; asm("fma.rn.f32x2 %0, %1, %2, %3;" : "=l"(d) : "l"(a), "l"(b), "l"(c)); return d;
}
__device__ __forceinline__ ull mul2(ull a, ull b) {
    ull d; asm("mul.rn.f32x2 %0, %1, %2;" : "=l"(d) : "l"(a), "l"(b)); return d;
}
__device__ __forceinline__ ull pack2(float x, float y) {
    ull d; asm("mov.b64 %0, {%1, %2};" : "=l"(d) : "f"(x), "f"(y)); return d;
}
__device__ __forceinline__ float2 unpk2(ull v) {
    float x, y; asm("mov.b64 {%0, %1}, %2;" : "=f"(x), "=f"(y) : "l"(v)); return make_float2(x, y);
}

// ---- scratch: fp32 intermediates + bf16 hi/lo operand copies ----
__device__ float g_q[ROWS * DM];
__device__ float g_lat[ROWS * DL];
__device__ float g_kv[ROWS * DM];
__device__ float g_att[ROWS * DM];

__device__ __nv_bfloat16 g_xhi[ROWS * DM],  g_xlo[ROWS * DM];
__device__ __nv_bfloat16 g_wqhi[DM * DM],   g_wqlo[DM * DM];
__device__ __nv_bfloat16 g_wkdhi[DM * DL],  g_wkdlo[DM * DL];
__device__ __nv_bfloat16 g_wkuhi[DL * DM],  g_wkulo[DL * DM];
__device__ __nv_bfloat16 g_wohi[DM * DM],   g_wolo[DM * DM];
__device__ __nv_bfloat16 g_lathi[ROWS * DL], g_latlo[ROWS * DL];
__device__ __nv_bfloat16 g_atthi[ROWS * DM], g_attlo[ROWS * DM];

// ---- fp32 -> bf16 hi/lo split (4 elems packed per ull) ----
__device__ __forceinline__ void split4(float4 v, ull& hi, ull& lo) {
    __nv_bfloat16 h0 = __float2bfloat16(v.x), h1 = __float2bfloat16(v.y);
    __nv_bfloat16 h2 = __float2bfloat16(v.z), h3 = __float2bfloat16(v.w);
    __nv_bfloat16 l0 = __float2bfloat16(v.x - __bfloat162float(h0));
    __nv_bfloat16 l1 = __float2bfloat16(v.y - __bfloat162float(h1));
    __nv_bfloat16 l2 = __float2bfloat16(v.z - __bfloat162float(h2));
    __nv_bfloat16 l3 = __float2bfloat16(v.w - __bfloat162float(h3));
    hi = (ull)__bfloat16_as_ushort(h0) | ((ull)__bfloat16_as_ushort(h1) << 16)
       | ((ull)__bfloat16_as_ushort(h2) << 32) | ((ull)__bfloat16_as_ushort(h3) << 48);
    lo = (ull)__bfloat16_as_ushort(l0) | ((ull)__bfloat16_as_ushort(l1) << 16)
       | ((ull)__bfloat16_as_ushort(l2) << 32) | ((ull)__bfloat16_as_ushort(l3) << 48);
}

__global__ __launch_bounds__(256) void splitf(const float4* __restrict__ src,
                                              ull* __restrict__ hi,
                                              ull* __restrict__ lo, int n4) {
    int i = blockIdx.x * 256 + threadIdx.x;
    if (i < n4) {
        ull h, l; split4(src[i], h, l);
        hi[i] = h; lo[i] = l;
    }
}

// ---- warp MMA plumbing ----
__device__ __forceinline__ u32 smem_u32(const void* p) {
    u32 a; asm("{ .reg .u64 t; cvta.to.shared.u64 t, %1; cvt.u32.u64 %0, t; }" : "=r"(a) : "l"(p)); return a;
}
__device__ __forceinline__ void cpa16(u32 dst, const void* src) {
    asm volatile("cp.async.cg.shared.global [%0], [%1], 16;" :: "r"(dst), "l"(src));
}
#define CP_COMMIT() asm volatile("cp.async.commit_group;" ::: "memory")
#define CP_WAIT1()  asm volatile("cp.async.wait_group 1;" ::: "memory")
#define CP_WAIT0()  asm volatile("cp.async.wait_group 0;" ::: "memory")

#define LDSM4(r, addr) \
    asm volatile("ldmatrix.sync.aligned.m8n8.x4.shared.b16 {%0,%1,%2,%3}, [%4];" \
        : "=r"((r)[0]), "=r"((r)[1]), "=r"((r)[2]), "=r"((r)[3]) : "r"(addr))
#define LDSM4T(r, addr) \
    asm volatile("ldmatrix.sync.aligned.m8n8.x4.trans.shared.b16 {%0,%1,%2,%3}, [%4];" \
        : "=r"((r)[0]), "=r"((r)[1]), "=r"((r)[2]), "=r"((r)[3]) : "r"(addr))

__device__ __forceinline__ void mma16(float* c, const u32* a, const u32* b) {
    asm volatile("mma.sync.aligned.m16n8k16.row.col.f32.bf16.bf16.f32 "
        "{%0,%1,%2,%3}, {%4,%5,%6,%7}, {%8,%9}, {%0,%1,%2,%3};"
        : "+f"(c[0]), "+f"(c[1]), "+f"(c[2]), "+f"(c[3])
        : "r"(a[0]), "r"(a[1]), "r"(a[2]), "r"(a[3]), "r"(b[0]), "r"(b[1]));
}

// ---------------------------------------------------------------------------
// bf16-split HMMA GEMM: C[M,N] = A@B (logically fp32), operands pre-split.
// 3 terms: Ahi*Bhi + Alo*Bhi + Ahi*Blo. M,N %128==0, K %32==0.
// 128x128 CTA tile, BK=32, 8 warps (64x32 warp tiles), cp.async double buffer.
// smem/buffer: Ahi 10240 + Alo 10240 + Bhi 8704 + Blo 8704 = 37888; x2 = 75776.
// A rows padded to 40 elems, B rows to 136 elems -> LDSM conflict-free.
// ---------------------------------------------------------------------------
#define ABUF 10240
#define BBUF 8704
#define SBUF 37888
__global__ __launch_bounds__(256, 2) void gemm_tc(
        const __nv_bfloat16* __restrict__ Ahi, const __nv_bfloat16* __restrict__ Alo,
        const __nv_bfloat16* __restrict__ Bhi, const __nv_bfloat16* __restrict__ Blo,
        float* __restrict__ C, int M, int N, int K) {
    extern __shared__ __align__(16) char sm[];
    const u32 smb = smem_u32(sm);

    const int tid = threadIdx.x, lane = tid & 31, wid = tid >> 5;
    const int bm = blockIdx.y << 7, bn = blockIdx.x << 7;
    const int wm = (wid >> 2) * 64, wn = (wid & 3) * 32;

    // staging: A: thread t -> row t>>1, 16 cols at (t&1)*16 ; B: row t>>3, 16 cols at (t&7)*16
    const int sm_m = tid >> 1, sm_kb = (tid & 1) << 4;
    const int sb_k = tid >> 3, sb_n = (tid & 7) << 4;
    const size_t gA = (size_t)(bm + sm_m) * K + sm_kb;
    const size_t gB = (size_t)sb_k * N + bn + sb_n;
    const u32 dA = (u32)(sm_m * 40 + sm_kb) * 2;
    const u32 dB = (u32)(sb_k * 136 + sb_n) * 2;

    // ldmatrix lane geometry
    const int lrow = (lane & 7) + ((lane >> 3) & 1) * 8;
    const int lcol = (lane >> 4) << 3;
    const u32 a_base = (u32)((wm + lrow) * 40 + lcol) * 2;  // + i*1280 + ks*32
    const u32 b_base = (u32)(lrow * 136 + wn + lcol) * 2;   // + ks*4352 + j*32

    float acc[4][4][4] = {};

    const int nCh = K >> 5;

    // stage chunk 0
    {
        const __nv_bfloat16 *pAh = Ahi + gA, *pAl = Alo + gA;
        const __nv_bfloat16 *pBh = Bhi + gB, *pBl = Blo + gB;
        cpa16(smb + dA, pAh);                  cpa16(smb + dA + 16, pAh + 8);
        cpa16(smb + ABUF + dA, pAl);           cpa16(smb + ABUF + dA + 16, pAl + 8);
        cpa16(smb + 2 * ABUF + dB, pBh);       cpa16(smb + 2 * ABUF + dB + 16, pBh + 8);
        cpa16(smb + 2 * ABUF + BBUF + dB, pBl); cpa16(smb + 2 * ABUF + BBUF + dB + 16, pBl + 8);
        CP_COMMIT();
    }

    for (int c = 0; c < nCh; c++) {
        if (c + 1 < nCh) {
            const u32 o = smb + ((c + 1) & 1) * SBUF;
            const int kc = (c + 1) << 5;
            const __nv_bfloat16 *pAh = Ahi + gA + kc, *pAl = Alo + gA + kc;
            const __nv_bfloat16 *pBh = Bhi + gB + (size_t)kc * N, *pBl = Blo + gB + (size_t)kc * N;
            cpa16(o + dA, pAh);                  cpa16(o + dA + 16, pAh + 8);
            cpa16(o + ABUF + dA, pAl);           cpa16(o + ABUF + dA + 16, pAl + 8);
            cpa16(o + 2 * ABUF + dB, pBh);       cpa16(o + 2 * ABUF + dB + 16, pBh + 8);
            cpa16(o + 2 * ABUF + BBUF + dB, pBl); cpa16(o + 2 * ABUF + BBUF + dB + 16, pBl + 8);
            CP_COMMIT();
            CP_WAIT1();
        } else {
            CP_WAIT0();
        }
        __syncthreads();

        const u32 o = smb + (c & 1) * SBUF;
        const u32 uAh = o, uAl = o + ABUF, uBh = o + 2 * ABUF, uBl = o + 2 * ABUF + BBUF;
#pragma unroll
        for (int ks = 0; ks < 2; ks++) {
            const u32 ka = a_base + ks * 32;          // 16 elems * 2B
            const u32 kb = b_base + ks * 4352;        // 16 rows * 136 * 2B
            u32 ah[4][4], bh[2][4];
#pragma unroll
            for (int i = 0; i < 4; i++) LDSM4(ah[i], uAh + ka + i * 1280);
#pragma unroll
            for (int j = 0; j < 2; j++) LDSM4T(bh[j], uBh + kb + j * 32);
#pragma unroll
            for (int i = 0; i < 4; i++)
#pragma unroll
                for (int jj = 0; jj < 4; jj++)
                    mma16(acc[i][jj], ah[i], &bh[jj >> 1][(jj & 1) * 2]);
            {
                u32 al[4][4];
#pragma unroll
                for (int i = 0; i < 4; i++) LDSM4(al[i], uAl + ka + i * 1280);
#pragma unroll
                for (int i = 0; i < 4; i++)
#pragma unroll
                    for (int jj = 0; jj < 4; jj++)
                        mma16(acc[i][jj], al[i], &bh[jj >> 1][(jj & 1) * 2]);
            }
            {
                u32 bl[2][4];
#pragma unroll
                for (int j = 0; j < 2; j++) LDSM4T(bl[j], uBl + kb + j * 32);
#pragma unroll
                for (int i = 0; i < 4; i++)
#pragma unroll
                    for (int jj = 0; jj < 4; jj++)
                        mma16(acc[i][jj], ah[i], &bl[jj >> 1][(jj & 1) * 2]);
            }
        }
        __syncthreads();
    }

    // epilogue
    const int g = lane >> 2, tg = lane & 3;
#pragma unroll
    for (int i = 0; i < 4; i++)
#pragma unroll
        for (int jj = 0; jj < 4; jj++) {
            const int r0 = bm + wm + i * 16 + g;
            const int c0 = bn + wn + jj * 8 + tg * 2;
            float* p = C + (size_t)r0 * N + c0;
            *(float2*)p = make_float2(acc[i][jj][0], acc[i][jj][1]);
            p += (size_t)8 * N;
            *(float2*)p = make_float2(acc[i][jj][2], acc[i][jj][3]);
        }
}

// ---------------------------------------------------------------------------
// Fused flash attention with f32x2 (unchanged from R8). K == V.
// ---------------------------------------------------------------------------
__global__ __launch_bounds__(256, 2) void mla_attn(const float* __restrict__ Q,
                                                   const float* __restrict__ KV,
                                                   float* __restrict__ O) {
    extern __shared__ __align__(16) float smf[];
    float* Qs   = smf;                 // 64 * 130
    float* Ks   = Qs + 64 * 130;       // 64 * 130
    float* Ps   = Ks + 64 * 130;       // 64 * 65
    float* mrow = Ps + 64 * 65;
    float* lrow = mrow + 64;
    float* arow = lrow + 64;

    const int tid = threadIdx.x;
    const int tx = tid & 15;
    const int ty = tid >> 4;
    const int qb = blockIdx.x;
    const int h  = blockIdx.y;
    const int b  = blockIdx.z;
    const float scale = 0.08838834764831843f;

    const float* qbase = Q  + ((size_t)b * SS + qb * 64) * DM + h * DH;
    const float* kbase = KV + (size_t)b * SS * DM + h * DH;

#pragma unroll
    for (int s = 0; s < 8; s++) {
        int idx = tid + s * 256;
        int r = idx >> 5;
        int c = (idx & 31) << 2;
        float4 v = *(const float4*)(qbase + (size_t)r * DM + c);
        *(ull*)&Qs[r * 130 + c]     = pack2(v.x * scale, v.y * scale);
        *(ull*)&Qs[r * 130 + c + 2] = pack2(v.z * scale, v.w * scale);
    }
    if (tid < 64) { mrow[tid] = -3.0e38f; lrow[tid] = 0.f; }

    ull o2[4][4] = {};

    for (int t = 0; t < SS / 64; t++) {
#pragma unroll
        for (int s = 0; s < 8; s++) {
            int idx = tid + s * 256;
            int r = idx >> 5;
            int c = (idx & 31) << 2;
            float4 v = *(const float4*)(kbase + (size_t)(t * 64 + r) * DM + c);
            *(ull*)&Ks[r * 130 + c]     = pack2(v.x, v.y);
            *(ull*)&Ks[r * 130 + c + 2] = pack2(v.z, v.w);
        }
        __syncthreads();

        ull sv[4][4] = {};
#pragma unroll 4
        for (int p = 0; p < 64; p++) {
            ull qv[4], kv4[4];
#pragma unroll
            for (int i = 0; i < 4; i++)
                qv[i] = *(const ull*)&Qs[(ty * 4 + i) * 130 + 2 * p];
#pragma unroll
            for (int j = 0; j < 4; j++)
                kv4[j] = *(const ull*)&Ks[(tx + 16 * j) * 130 + 2 * p];
#pragma unroll
            for (int i = 0; i < 4; i++)
#pragma unroll
                for (int j = 0; j < 4; j++)
                    sv[i][j] = ffma2(qv[i], kv4[j], sv[i][j]);
        }
#pragma unroll
        for (int i = 0; i < 4; i++)
#pragma unroll
            for (int j = 0; j < 4; j++) {
                float2 e = unpk2(sv[i][j]);
                Ps[(ty * 4 + i) * 65 + tx + 16 * j] = e.x + e.y;
            }
        __syncthreads();

        {
            int row = tid >> 2;
            int seg = tid & 3;
            float* pr = &Ps[row * 65 + seg * 16];
            float mloc = -3.0e38f;
#pragma unroll
            for (int c = 0; c < 16; c++) mloc = fmaxf(mloc, pr[c]);
            mloc = fmaxf(mloc, __shfl_xor_sync(0xffffffffu, mloc, 1));
            mloc = fmaxf(mloc, __shfl_xor_sync(0xffffffffu, mloc, 2));
            float mold = mrow[row];
            float mnew = fmaxf(mold, mloc);
            float sloc = 0.f;
#pragma unroll
            for (int c = 0; c < 16; c++) {
                float p = __expf(pr[c] - mnew);
                pr[c] = p;
                sloc += p;
            }
            sloc += __shfl_xor_sync(0xffffffffu, sloc, 1);
            sloc += __shfl_xor_sync(0xffffffffu, sloc, 2);
            if (seg == 0) {
                float al = __expf(mold - mnew);
                arow[row] = al;
                mrow[row] = mnew;
                lrow[row] = lrow[row] * al + sloc;
            }
        }
        __syncthreads();

#pragma unroll
        for (int i = 0; i < 4; i++) {
            float al = arow[ty * 4 + i];
            ull al2 = pack2(al, al);
#pragma unroll
            for (int m = 0; m < 4; m++) o2[i][m] = mul2(o2[i][m], al2);
        }
#pragma unroll 4
        for (int kk = 0; kk < 64; kk++) {
            ull pd[4], vv[4];
#pragma unroll
            for (int i = 0; i < 4; i++) {
                float p = Ps[(ty * 4 + i) * 65 + kk];
                pd[i] = pack2(p, p);
            }
#pragma unroll
            for (int m = 0; m < 4; m++)
                vv[m] = *(const ull*)&Ks[kk * 130 + 32 * m + 2 * tx];
#pragma unroll
            for (int i = 0; i < 4; i++)
#pragma unroll
                for (int m = 0; m < 4; m++)
                    o2[i][m] = ffma2(pd[i], vv[m], o2[i][m]);
        }
        __syncthreads();
    }

#pragma unroll
    for (int i = 0; i < 4; i++) {
        float inv = 1.f / lrow[ty * 4 + i];
        float* op = O + ((size_t)b * SS + qb * 64 + ty * 4 + i) * DM + h * DH;
#pragma unroll
        for (int m = 0; m < 4; m++) {
            float2 e = unpk2(o2[i][m]);
            *(float2*)(op + 32 * m + 2 * tx) = make_float2(e.x * inv, e.y * inv);
        }
    }
}

// ---------------------------------------------------------------------------
static inline void run_split(const float* src, __nv_bfloat16* hi, __nv_bfloat16* lo, int n) {
    int n4 = n >> 2;
    splitf<<<(n4 + 255) / 256, 256>>>((const float4*)src, (ull*)hi, (ull*)lo, n4);
}

extern "C" void kernel_launch(void* const* d_in, const int* in_sizes, int n_in,
                              void* d_out, int out_size) {
    const float* x    = (const float*)d_in[0];   // [2,2048,2048]
    const float* W_q  = (const float*)d_in[1];   // [2048, 2048]
    const float* W_kd = (const float*)d_in[2];   // [2048, 512]
    const float* W_ku = (const float*)d_in[3];   // [512, 2048]
    const float* W_o  = (const float*)d_in[4];   // [2048, 2048]
    float* out = (float*)d_out;

    float *pq, *pl, *pkv, *pa;
    cudaGetSymbolAddress((void**)&pq,  g_q);
    cudaGetSymbolAddress((void**)&pl,  g_lat);
    cudaGetSymbolAddress((void**)&pkv, g_kv);
    cudaGetSymbolAddress((void**)&pa,  g_att);

    __nv_bfloat16 *xhi, *xlo, *wqhi, *wqlo, *wkdhi, *wkdlo, *wkuhi, *wkulo;
    __nv_bfloat16 *wohi, *wolo, *lathi, *latlo, *atthi, *attlo;
    cudaGetSymbolAddress((void**)&xhi,  g_xhi);   cudaGetSymbolAddress((void**)&xlo,  g_xlo);
    cudaGetSymbolAddress((void**)&wqhi, g_wqhi);  cudaGetSymbolAddress((void**)&wqlo, g_wqlo);
    cudaGetSymbolAddress((void**)&wkdhi,g_wkdhi); cudaGetSymbolAddress((void**)&wkdlo,g_wkdlo);
    cudaGetSymbolAddress((void**)&wkuhi,g_wkuhi); cudaGetSymbolAddress((void**)&wkulo,g_wkulo);
    cudaGetSymbolAddress((void**)&wohi, g_wohi);  cudaGetSymbolAddress((void**)&wolo, g_wolo);
    cudaGetSymbolAddress((void**)&lathi,g_lathi); cudaGetSymbolAddress((void**)&latlo,g_latlo);
    cudaGetSymbolAddress((void**)&atthi,g_atthi); cudaGetSymbolAddress((void**)&attlo,g_attlo);

    dim3 blk(256);
    const int gsm = 2 * SBUF;  // 75776
    cudaFuncSetAttribute(gemm_tc, cudaFuncAttributeMaxDynamicSharedMemorySize, gsm);

    // split all static operands
    run_split(x,    xhi,  xlo,  ROWS * DM);
    run_split(W_q,  wqhi, wqlo, DM * DM);
    run_split(W_kd, wkdhi, wkdlo, DM * DL);
    run_split(W_ku, wkuhi, wkulo, DL * DM);
    run_split(W_o,  wohi, wolo, DM * DM);

    // q = x @ W_q
    gemm_tc<<<dim3(DM / 128, ROWS / 128), blk, gsm>>>(xhi, xlo, wqhi, wqlo, pq, ROWS, DM, DM);
    // latent = x @ W_kv_down
    gemm_tc<<<dim3(DL / 128, ROWS / 128), blk, gsm>>>(xhi, xlo, wkdhi, wkdlo, pl, ROWS, DL, DM);
    run_split(pl, lathi, latlo, ROWS * DL);
    // kv = latent @ W_kv_up
    gemm_tc<<<dim3(DM / 128, ROWS / 128), blk, gsm>>>(lathi, latlo, wkuhi, wkulo, pkv, ROWS, DM, DL);

    // fused attention (fp32)
    size_t smem = (size_t)(64 * 130 * 2 + 64 * 65 + 3 * 64) * sizeof(float); // 83968
    cudaFuncSetAttribute(mla_attn, cudaFuncAttributeMaxDynamicSharedMemorySize, (int)smem);
    mla_attn<<<dim3(SS / 64, NH, BB), blk, smem>>>(pq, pkv, pa);

    // out = attn @ W_o
    run_split(pa, atthi, attlo, ROWS * DM);
    gemm_tc<<<dim3(DM / 128, ROWS / 128), blk, gsm>>>(atthi, attlo, wohi, wolo, out, ROWS, DM, DM);
}

// round 11
// speedup vs baseline: 3.0257x; 1.6256x over previous
#include <cuda_runtime.h>
#include <cuda_bf16.h>

#define DM 2048      // d_model
#define NH 16        // heads
#define DH 128       // d_head
#define DL 512       // d_latent
#define BB 2         // batch
#define SS 2048      // seq
#define ROWS (BB * SS)   // 4096

typedef unsigned long long ull;
typedef unsigned int u32;

// ---- scratch: fp32 intermediates + bf16 hi/lo operand copies ----
__device__ float g_q[ROWS * DM];
__device__ float g_lat[ROWS * DL];
__device__ float g_kv[ROWS * DM];
__device__ float g_att[ROWS * DM];

__device__ __nv_bfloat16 g_xhi[ROWS * DM],  g_xlo[ROWS * DM];
__device__ __nv_bfloat16 g_wqhi[DM * DM],   g_wqlo[DM * DM];
__device__ __nv_bfloat16 g_wkdhi[DM * DL],  g_wkdlo[DM * DL];
__device__ __nv_bfloat16 g_wkuhi[DL * DM],  g_wkulo[DL * DM];
__device__ __nv_bfloat16 g_wohi[DM * DM],   g_wolo[DM * DM];
__device__ __nv_bfloat16 g_lathi[ROWS * DL], g_latlo[ROWS * DL];
__device__ __nv_bfloat16 g_atthi[ROWS * DM], g_attlo[ROWS * DM];
__device__ __nv_bfloat16 g_qhi[ROWS * DM],  g_qlo[ROWS * DM];
__device__ __nv_bfloat16 g_kvhi[ROWS * DM], g_kvlo[ROWS * DM];

// ---- fp32 -> bf16 hi/lo split ----
__device__ __forceinline__ void split4(float4 v, ull& hi, ull& lo) {
    __nv_bfloat16 h0 = __float2bfloat16(v.x), h1 = __float2bfloat16(v.y);
    __nv_bfloat16 h2 = __float2bfloat16(v.z), h3 = __float2bfloat16(v.w);
    __nv_bfloat16 l0 = __float2bfloat16(v.x - __bfloat162float(h0));
    __nv_bfloat16 l1 = __float2bfloat16(v.y - __bfloat162float(h1));
    __nv_bfloat16 l2 = __float2bfloat16(v.z - __bfloat162float(h2));
    __nv_bfloat16 l3 = __float2bfloat16(v.w - __bfloat162float(h3));
    hi = (ull)__bfloat16_as_ushort(h0) | ((ull)__bfloat16_as_ushort(h1) << 16)
       | ((ull)__bfloat16_as_ushort(h2) << 32) | ((ull)__bfloat16_as_ushort(h3) << 48);
    lo = (ull)__bfloat16_as_ushort(l0) | ((ull)__bfloat16_as_ushort(l1) << 16)
       | ((ull)__bfloat16_as_ushort(l2) << 32) | ((ull)__bfloat16_as_ushort(l3) << 48);
}

__global__ __launch_bounds__(256) void splitf(const float4* __restrict__ src,
                                              ull* __restrict__ hi,
                                              ull* __restrict__ lo, int n4) {
    int i = blockIdx.x * 256 + threadIdx.x;
    if (i < n4) {
        ull h, l; split4(src[i], h, l);
        hi[i] = h; lo[i] = l;
    }
}

// ---- warp MMA plumbing ----
__device__ __forceinline__ u32 smem_u32(const void* p) {
    u32 a; asm("{ .reg .u64 t; cvta.to.shared.u64 t, %1; cvt.u32.u64 %0, t; }" : "=r"(a) : "l"(p)); return a;
}
__device__ __forceinline__ void cpa16(u32 dst, const void* src) {
    asm volatile("cp.async.cg.shared.global [%0], [%1], 16;" :: "r"(dst), "l"(src));
}
#define CP_COMMIT() asm volatile("cp.async.commit_group;" ::: "memory")
#define CP_WAIT1()  asm volatile("cp.async.wait_group 1;" ::: "memory")
#define CP_WAIT0()  asm volatile("cp.async.wait_group 0;" ::: "memory")

#define LDSM4(r, addr) \
    asm volatile("ldmatrix.sync.aligned.m8n8.x4.shared.b16 {%0,%1,%2,%3}, [%4];" \
        : "=r"((r)[0]), "=r"((r)[1]), "=r"((r)[2]), "=r"((r)[3]) : "r"(addr))
#define LDSM4T(r, addr) \
    asm volatile("ldmatrix.sync.aligned.m8n8.x4.trans.shared.b16 {%0,%1,%2,%3}, [%4];" \
        : "=r"((r)[0]), "=r"((r)[1]), "=r"((r)[2]), "=r"((r)[3]) : "r"(addr))

__device__ __forceinline__ void mma16(float* c, const u32* a, const u32* b) {
    asm volatile("mma.sync.aligned.m16n8k16.row.col.f32.bf16.bf16.f32 "
        "{%0,%1,%2,%3}, {%4,%5,%6,%7}, {%8,%9}, {%0,%1,%2,%3};"
        : "+f"(c[0]), "+f"(c[1]), "+f"(c[2]), "+f"(c[3])
        : "r"(a[0]), "r"(a[1]), "r"(a[2]), "r"(a[3]), "r"(b[0]), "r"(b[1]));
}

// fast exp on the FMA pipe (no MUFU): 2^(x*log2e), deg-5 Taylor, err ~2e-6
__device__ __forceinline__ float fexp(float x) {
    x = fmaxf(x, -80.f);
    float y = fmaf(x, 1.44269504f, 12582912.f);
    int ni = __float_as_int(y) - __float_as_int(12582912.f);
    float n = y - 12582912.f;
    float f = fmaf(x, 1.44269504f, -n);
    float p = 0.0013333558f;
    p = fmaf(p, f, 0.0096181291f);
    p = fmaf(p, f, 0.055504109f);
    p = fmaf(p, f, 0.24022651f);
    p = fmaf(p, f, 0.69314718f);
    p = fmaf(p, f, 1.0f);
    return p * __int_as_float((ni + 127) << 23);
}

// ---------------------------------------------------------------------------
// bf16-split HMMA GEMM (unchanged from R10).
// ---------------------------------------------------------------------------
#define ABUF 10240
#define BBUF 8704
#define SBUF 37888
__global__ __launch_bounds__(256, 2) void gemm_tc(
        const __nv_bfloat16* __restrict__ Ahi, const __nv_bfloat16* __restrict__ Alo,
        const __nv_bfloat16* __restrict__ Bhi, const __nv_bfloat16* __restrict__ Blo,
        float* __restrict__ C, int M, int N, int K) {
    extern __shared__ __align__(16) char sm[];
    const u32 smb = smem_u32(sm);

    const int tid = threadIdx.x, lane = tid & 31, wid = tid >> 5;
    const int bm = blockIdx.y << 7, bn = blockIdx.x << 7;
    const int wm = (wid >> 2) * 64, wn = (wid & 3) * 32;

    const int sm_m = tid >> 1, sm_kb = (tid & 1) << 4;
    const int sb_k = tid >> 3, sb_n = (tid & 7) << 4;
    const size_t gA = (size_t)(bm + sm_m) * K + sm_kb;
    const size_t gB = (size_t)sb_k * N + bn + sb_n;
    const u32 dA = (u32)(sm_m * 40 + sm_kb) * 2;
    const u32 dB = (u32)(sb_k * 136 + sb_n) * 2;

    const int lrow = (lane & 7) + ((lane >> 3) & 1) * 8;
    const int lcol = (lane >> 4) << 3;
    const u32 a_base = (u32)((wm + lrow) * 40 + lcol) * 2;
    const u32 b_base = (u32)(lrow * 136 + wn + lcol) * 2;

    float acc[4][4][4] = {};
    const int nCh = K >> 5;

    {
        const __nv_bfloat16 *pAh = Ahi + gA, *pAl = Alo + gA;
        const __nv_bfloat16 *pBh = Bhi + gB, *pBl = Blo + gB;
        cpa16(smb + dA, pAh);                  cpa16(smb + dA + 16, pAh + 8);
        cpa16(smb + ABUF + dA, pAl);           cpa16(smb + ABUF + dA + 16, pAl + 8);
        cpa16(smb + 2 * ABUF + dB, pBh);       cpa16(smb + 2 * ABUF + dB + 16, pBh + 8);
        cpa16(smb + 2 * ABUF + BBUF + dB, pBl); cpa16(smb + 2 * ABUF + BBUF + dB + 16, pBl + 8);
        CP_COMMIT();
    }

    for (int c = 0; c < nCh; c++) {
        if (c + 1 < nCh) {
            const u32 o = smb + ((c + 1) & 1) * SBUF;
            const int kc = (c + 1) << 5;
            const __nv_bfloat16 *pAh = Ahi + gA + kc, *pAl = Alo + gA + kc;
            const __nv_bfloat16 *pBh = Bhi + gB + (size_t)kc * N, *pBl = Blo + gB + (size_t)kc * N;
            cpa16(o + dA, pAh);                  cpa16(o + dA + 16, pAh + 8);
            cpa16(o + ABUF + dA, pAl);           cpa16(o + ABUF + dA + 16, pAl + 8);
            cpa16(o + 2 * ABUF + dB, pBh);       cpa16(o + 2 * ABUF + dB + 16, pBh + 8);
            cpa16(o + 2 * ABUF + BBUF + dB, pBl); cpa16(o + 2 * ABUF + BBUF + dB + 16, pBl + 8);
            CP_COMMIT();
            CP_WAIT1();
        } else {
            CP_WAIT0();
        }
        __syncthreads();

        const u32 o = smb + (c & 1) * SBUF;
        const u32 uAh = o, uAl = o + ABUF, uBh = o + 2 * ABUF, uBl = o + 2 * ABUF + BBUF;
#pragma unroll
        for (int ks = 0; ks < 2; ks++) {
            const u32 ka = a_base + ks * 32;
            const u32 kb = b_base + ks * 4352;
            u32 ah[4][4], bh[2][4];
#pragma unroll
            for (int i = 0; i < 4; i++) LDSM4(ah[i], uAh + ka + i * 1280);
#pragma unroll
            for (int j = 0; j < 2; j++) LDSM4T(bh[j], uBh + kb + j * 32);
#pragma unroll
            for (int i = 0; i < 4; i++)
#pragma unroll
                for (int jj = 0; jj < 4; jj++)
                    mma16(acc[i][jj], ah[i], &bh[jj >> 1][(jj & 1) * 2]);
            {
                u32 al[4][4];
#pragma unroll
                for (int i = 0; i < 4; i++) LDSM4(al[i], uAl + ka + i * 1280);
#pragma unroll
                for (int i = 0; i < 4; i++)
#pragma unroll
                    for (int jj = 0; jj < 4; jj++)
                        mma16(acc[i][jj], al[i], &bh[jj >> 1][(jj & 1) * 2]);
            }
            {
                u32 bl[2][4];
#pragma unroll
                for (int j = 0; j < 2; j++) LDSM4T(bl[j], uBl + kb + j * 32);
#pragma unroll
                for (int i = 0; i < 4; i++)
#pragma unroll
                    for (int jj = 0; jj < 4; jj++)
                        mma16(acc[i][jj], ah[i], &bl[jj >> 1][(jj & 1) * 2]);
            }
        }
        __syncthreads();
    }

    const int g = lane >> 2, tg = lane & 3;
#pragma unroll
    for (int i = 0; i < 4; i++)
#pragma unroll
        for (int jj = 0; jj < 4; jj++) {
            const int r0 = bm + wm + i * 16 + g;
            const int c0 = bn + wn + jj * 8 + tg * 2;
            float* p = C + (size_t)r0 * N + c0;
            *(float2*)p = make_float2(acc[i][jj][0], acc[i][jj][1]);
            p += (size_t)8 * N;
            *(float2*)p = make_float2(acc[i][jj][2], acc[i][jj][3]);
        }
}

// ---------------------------------------------------------------------------
// HMMA flash attention. 64 q rows / CTA, KV tiles of 64, 8 warps.
// QK^T and PV both bf16-split 3-term; softmax with poly exp on FMA pipe.
// KV smem tile [kvrow][d] (stride 136) serves both MMAs:
//   QK B-view: [n=kvrow][k=d] via LDSM4  (n8 frags {r0,r2},{r1,r3})
//   PV B-view: [k=kvrow][n=d] via LDSM4T (n8 frags {r0,r1},{r2,r3})
// smem: Qhi/Qlo/Khi/Klo 4x17408 + S 17408 + Phi/Plo 2x9216 + stats 768 = 106240
// ---------------------------------------------------------------------------
#define ATS 136
#define PSTR 72
#define SSTR 68
#define OQH 0
#define OQL 17408
#define OKH 34816
#define OKL 52224
#define OSS 69632
#define OPH 87040
#define OPL 96256
#define OST 105472
#define ATT_SMEM 106240

__global__ __launch_bounds__(256, 2) void mla_attn_tc(
        const __nv_bfloat16* __restrict__ Qhi, const __nv_bfloat16* __restrict__ Qlo,
        const __nv_bfloat16* __restrict__ Khi, const __nv_bfloat16* __restrict__ Klo,
        float* __restrict__ O) {
    extern __shared__ __align__(16) char sm[];
    const u32 smb = smem_u32(sm);
    float* Sf   = (float*)(sm + OSS);
    float* mrow = (float*)(sm + OST);
    float* lrow = (float*)(sm + OST + 256);
    float* arow = (float*)(sm + OST + 512);

    const int tid = threadIdx.x, lane = tid & 31, wid = tid >> 5;
    const int qb = blockIdx.x, h = blockIdx.y, b = blockIdx.z;
    const int wrow = (wid & 3) * 16;   // warp q-row base
    const int wn   = (wid >> 2) * 32;  // QK kv-col base
    const int wd   = (wid >> 2) * 64;  // PV d-col base
    const float scale = 0.08838834764831843f;

    const size_t qoff = ((size_t)b * SS + qb * 64) * DM + h * DH;
    const size_t koff = (size_t)b * SS * DM + h * DH;

    // Q tile (hi/lo) via cp.async
#pragma unroll
    for (int s = 0; s < 4; s++) {
        int id = tid + s * 256;
        int r = id >> 4, c = (id & 15) * 8;
        u32 d = (u32)(r * ATS + c) * 2;
        cpa16(smb + OQH + d, Qhi + qoff + (size_t)r * DM + c);
        cpa16(smb + OQL + d, Qlo + qoff + (size_t)r * DM + c);
    }
    CP_COMMIT();
    if (tid < 64) { mrow[tid] = -3.0e38f; lrow[tid] = 0.f; }

    const int lr = (lane & 7) + ((lane >> 3) & 1) * 8;
    const int lc = (lane >> 4) << 3;
    const int g = lane >> 2, tg = lane & 3;

    float of[8][4] = {};

    for (int t = 0; t < SS / 64; t++) {
        __syncthreads();   // prev PV done before KV overwrite; also covers stats init
        // stage KV tile
#pragma unroll
        for (int s = 0; s < 4; s++) {
            int id = tid + s * 256;
            int r = id >> 4, c = (id & 15) * 8;
            u32 d = (u32)(r * ATS + c) * 2;
            const size_t gsrc = koff + (size_t)(t * 64 + r) * DM + c;
            cpa16(smb + OKH + d, Khi + gsrc);
            cpa16(smb + OKL + d, Klo + gsrc);
        }
        CP_COMMIT();
        CP_WAIT0();
        __syncthreads();

        // ---- S = Q @ K^T (3-term split) ----
        float sv[4][4] = {};
#pragma unroll
        for (int kc = 0; kc < 8; kc++) {
            u32 qa = smb + OQH + (u32)((wrow + lr) * ATS + kc * 16 + lc) * 2;
            u32 ah[4], al[4];
            LDSM4(ah, qa);
            LDSM4(al, qa + (OQL - OQH));
#pragma unroll
            for (int nc = 0; nc < 2; nc++) {
                u32 ka = smb + OKH + (u32)((wn + nc * 16 + lr) * ATS + kc * 16 + lc) * 2;
                u32 bh[4], bl[4];
                LDSM4(bh, ka);
                LDSM4(bl, ka + (OKL - OKH));
                u32 f0h[2] = {bh[0], bh[2]}, f1h[2] = {bh[1], bh[3]};
                u32 f0l[2] = {bl[0], bl[2]}, f1l[2] = {bl[1], bl[3]};
                mma16(sv[nc * 2 + 0], ah, f0h);
                mma16(sv[nc * 2 + 1], ah, f1h);
                mma16(sv[nc * 2 + 0], al, f0h);
                mma16(sv[nc * 2 + 1], al, f1h);
                mma16(sv[nc * 2 + 0], ah, f0l);
                mma16(sv[nc * 2 + 1], ah, f1l);
            }
        }
        // write S -> smem
#pragma unroll
        for (int f = 0; f < 4; f++) {
            int col = wn + f * 8 + tg * 2;
            *(float2*)&Sf[(wrow + g) * SSTR + col]     = make_float2(sv[f][0], sv[f][1]);
            *(float2*)&Sf[(wrow + g + 8) * SSTR + col] = make_float2(sv[f][2], sv[f][3]);
        }
        __syncthreads();

        // ---- online softmax (4 threads/row, poly exp, split P) ----
        {
            int row = tid >> 2, seg = tid & 3;
            const float* sp = &Sf[row * SSTR + seg * 16];
            float x[16];
            float mloc = -3.0e38f;
#pragma unroll
            for (int c = 0; c < 16; c++) { x[c] = sp[c] * scale; mloc = fmaxf(mloc, x[c]); }
            mloc = fmaxf(mloc, __shfl_xor_sync(0xffffffffu, mloc, 1));
            mloc = fmaxf(mloc, __shfl_xor_sync(0xffffffffu, mloc, 2));
            float mold = mrow[row];
            float mnew = fmaxf(mold, mloc);
            float sloc = 0.f;
            u32* php = (u32*)(sm + OPH) + row * (PSTR / 2) + seg * 8;
            u32* plp = (u32*)(sm + OPL) + row * (PSTR / 2) + seg * 8;
#pragma unroll
            for (int c2 = 0; c2 < 8; c2++) {
                float p0 = fexp(x[2 * c2] - mnew);
                float p1 = fexp(x[2 * c2 + 1] - mnew);
                sloc += p0 + p1;
                __nv_bfloat162 hp = __floats2bfloat162_rn(p0, p1);
                float l0 = p0 - __bfloat162float(hp.x);
                float l1 = p1 - __bfloat162float(hp.y);
                __nv_bfloat162 lp = __floats2bfloat162_rn(l0, l1);
                php[c2] = *(u32*)&hp;
                plp[c2] = *(u32*)&lp;
            }
            sloc += __shfl_xor_sync(0xffffffffu, sloc, 1);
            sloc += __shfl_xor_sync(0xffffffffu, sloc, 2);
            if (seg == 0) {
                float al = fexp(mold - mnew);
                arow[row] = al;
                mrow[row] = mnew;
                lrow[row] = lrow[row] * al + sloc;
            }
        }
        __syncthreads();

        // ---- O = alpha*O + P @ V (3-term split) ----
        {
            float a0 = arow[wrow + g], a1 = arow[wrow + g + 8];
#pragma unroll
            for (int f = 0; f < 8; f++) {
                of[f][0] *= a0; of[f][1] *= a0;
                of[f][2] *= a1; of[f][3] *= a1;
            }
        }
#pragma unroll
        for (int kc = 0; kc < 4; kc++) {
            u32 pa = smb + OPH + (u32)((wrow + lr) * PSTR + kc * 16 + lc) * 2;
            u32 ah[4], al[4];
            LDSM4(ah, pa);
            LDSM4(al, pa + (OPL - OPH));
#pragma unroll
            for (int ns = 0; ns < 4; ns++) {
                u32 va = smb + OKH + (u32)((kc * 16 + lr) * ATS + wd + ns * 16 + lc) * 2;
                u32 bh[4], bl[4];
                LDSM4T(bh, va);
                LDSM4T(bl, va + (OKL - OKH));
                mma16(of[ns * 2 + 0], ah, &bh[0]);
                mma16(of[ns * 2 + 1], ah, &bh[2]);
                mma16(of[ns * 2 + 0], al, &bh[0]);
                mma16(of[ns * 2 + 1], al, &bh[2]);
                mma16(of[ns * 2 + 0], ah, &bl[0]);
                mma16(of[ns * 2 + 1], ah, &bl[2]);
            }
        }
    }

    // normalize + store
    float inv0 = 1.f / lrow[wrow + g];
    float inv1 = 1.f / lrow[wrow + g + 8];
    const size_t obase = ((size_t)b * SS + qb * 64 + wrow) * DM + h * DH;
#pragma unroll
    for (int f = 0; f < 8; f++) {
        int col = wd + f * 8 + tg * 2;
        *(float2*)(O + obase + (size_t)g * DM + col) =
            make_float2(of[f][0] * inv0, of[f][1] * inv0);
        *(float2*)(O + obase + (size_t)(g + 8) * DM + col) =
            make_float2(of[f][2] * inv1, of[f][3] * inv1);
    }
}

// ---------------------------------------------------------------------------
static inline void run_split(const float* src, __nv_bfloat16* hi, __nv_bfloat16* lo, int n) {
    int n4 = n >> 2;
    splitf<<<(n4 + 255) / 256, 256>>>((const float4*)src, (ull*)hi, (ull*)lo, n4);
}

extern "C" void kernel_launch(void* const* d_in, const int* in_sizes, int n_in,
                              void* d_out, int out_size) {
    const float* x    = (const float*)d_in[0];
    const float* W_q  = (const float*)d_in[1];
    const float* W_kd = (const float*)d_in[2];
    const float* W_ku = (const float*)d_in[3];
    const float* W_o  = (const float*)d_in[4];
    float* out = (float*)d_out;

    float *pq, *pl, *pkv, *pa;
    cudaGetSymbolAddress((void**)&pq,  g_q);
    cudaGetSymbolAddress((void**)&pl,  g_lat);
    cudaGetSymbolAddress((void**)&pkv, g_kv);
    cudaGetSymbolAddress((void**)&pa,  g_att);

    __nv_bfloat16 *xhi, *xlo, *wqhi, *wqlo, *wkdhi, *wkdlo, *wkuhi, *wkulo;
    __nv_bfloat16 *wohi, *wolo, *lathi, *latlo, *atthi, *attlo;
    __nv_bfloat16 *qhi, *qlo, *kvhi, *kvlo;
    cudaGetSymbolAddress((void**)&xhi,  g_xhi);   cudaGetSymbolAddress((void**)&xlo,  g_xlo);
    cudaGetSymbolAddress((void**)&wqhi, g_wqhi);  cudaGetSymbolAddress((void**)&wqlo, g_wqlo);
    cudaGetSymbolAddress((void**)&wkdhi,g_wkdhi); cudaGetSymbolAddress((void**)&wkdlo,g_wkdlo);
    cudaGetSymbolAddress((void**)&wkuhi,g_wkuhi); cudaGetSymbolAddress((void**)&wkulo,g_wkulo);
    cudaGetSymbolAddress((void**)&wohi, g_wohi);  cudaGetSymbolAddress((void**)&wolo, g_wolo);
    cudaGetSymbolAddress((void**)&lathi,g_lathi); cudaGetSymbolAddress((void**)&latlo,g_latlo);
    cudaGetSymbolAddress((void**)&atthi,g_atthi); cudaGetSymbolAddress((void**)&attlo,g_attlo);
    cudaGetSymbolAddress((void**)&qhi,  g_qhi);   cudaGetSymbolAddress((void**)&qlo,  g_qlo);
    cudaGetSymbolAddress((void**)&kvhi, g_kvhi);  cudaGetSymbolAddress((void**)&kvlo, g_kvlo);

    dim3 blk(256);
    const int gsm = 2 * SBUF;  // 75776
    cudaFuncSetAttribute(gemm_tc, cudaFuncAttributeMaxDynamicSharedMemorySize, gsm);
    cudaFuncSetAttribute(mla_attn_tc, cudaFuncAttributeMaxDynamicSharedMemorySize, ATT_SMEM);

    // split static operands
    run_split(x,    xhi,  xlo,  ROWS * DM);
    run_split(W_q,  wqhi, wqlo, DM * DM);
    run_split(W_kd, wkdhi, wkdlo, DM * DL);
    run_split(W_ku, wkuhi, wkulo, DL * DM);
    run_split(W_o,  wohi, wolo, DM * DM);

    // q = x @ W_q ; split
    gemm_tc<<<dim3(DM / 128, ROWS / 128), blk, gsm>>>(xhi, xlo, wqhi, wqlo, pq, ROWS, DM, DM);
    run_split(pq, qhi, qlo, ROWS * DM);
    // latent = x @ W_kv_down ; split
    gemm_tc<<<dim3(DL / 128, ROWS / 128), blk, gsm>>>(xhi, xlo, wkdhi, wkdlo, pl, ROWS, DL, DM);
    run_split(pl, lathi, latlo, ROWS * DL);
    // kv = latent @ W_kv_up ; split
    gemm_tc<<<dim3(DM / 128, ROWS / 128), blk, gsm>>>(lathi, latlo, wkuhi, wkulo, pkv, ROWS, DM, DL);
    run_split(pkv, kvhi, kvlo, ROWS * DM);

    // fused attention (HMMA)
    mla_attn_tc<<<dim3(SS / 64, NH, BB), blk, ATT_SMEM>>>(qhi, qlo, kvhi, kvlo, pa);

    // out = attn @ W_o
    run_split(pa, atthi, attlo, ROWS * DM);
    gemm_tc<<<dim3(DM / 128, ROWS / 128), blk, gsm>>>(atthi, attlo, wohi, wolo, out, ROWS, DM, DM);
}